// round 5
// baseline (speedup 1.0000x reference)
#include <cuda_runtime.h>

// out[k] = sum_d x[d] * S[d][k],  S[d][k] = sum_n M[n][d][k].
// M flattened to 400 float4 rows (row p = (n,d), comps = k); lane t owns rows
// p = t + 32j; since 32 % 4 == 0, d = t & 3 is fixed per lane.
//
// Accumulation is pure FADDs (x decoupled; its L2 load overlaps the chain),
// then one FMUL by x[d] per component. After that every lane holds partial
// sums of the SAME 4 output components, so the 32-lane reduction is done via
// a transposed smem dump (conflict-free, padded rows) + a 4-lane serial
// finish — post-load critical path ~90 cyc vs ~165 for the 5-stage shfl
// butterfly (SHFL lat 26 each, 5 dependent stages).

__global__ void __launch_bounds__(32, 1)
bigfanout_kernel(const float* __restrict__ x,
                 const float* __restrict__ matrices,
                 float* __restrict__ out) {
    // Row stride 36 floats (144 B): STS conflict-free per component row,
    // rows 16B-aligned for LDS.128, and the 4 reader lanes hit disjoint banks.
    __shared__ __align__(16) float sm[4 * 36];

    const int t = threadIdx.x;            // 0..31
    const float xv = x[t & 3];            // issued early; consumed late

    const float4* __restrict__ rows = reinterpret_cast<const float4*>(matrices);

    // Pure-add accumulation, dual accumulators to halve the FADD chain.
    float e0 = 0.f, e1 = 0.f, e2 = 0.f, e3 = 0.f;
    float o0 = 0.f, o1 = 0.f, o2 = 0.f, o3 = 0.f;

    #pragma unroll
    for (int j = 0; j < 12; j += 2) {
        float4 re = rows[t + 32 * j];
        float4 ro = rows[t + 32 * (j + 1)];
        e0 += re.x;  e1 += re.y;  e2 += re.z;  e3 += re.w;
        o0 += ro.x;  o1 += ro.y;  o2 += ro.z;  o3 += ro.w;
    }

    // Tail: rows 384..399, lanes 0..15. 384 % 4 == 0 so d = t&3 still holds.
    if (t < 16) {
        float4 r = rows[384 + t];
        e0 += r.x;  e1 += r.y;  e2 += r.z;  e3 += r.w;
    }

    // Apply x[d] once per component (first consumer of the x load), then
    // dump transposed: smem row k holds the 32 lane-partials of out[k].
    sm[0 * 36 + t] = (e0 + o0) * xv;
    sm[1 * 36 + t] = (e1 + o1) * xv;
    sm[2 * 36 + t] = (e2 + o2) * xv;
    sm[3 * 36 + t] = (e3 + o3) * xv;

    __syncwarp();

    // Lanes 0..3: sum component row t (32 floats = 8x LDS.128, overlapped).
    if (t < 4) {
        const float4* r4 = reinterpret_cast<const float4*>(&sm[t * 36]);
        float4 a = r4[0], b = r4[1], c = r4[2], d = r4[3];
        float4 e = r4[4], f = r4[5], g = r4[6], h = r4[7];

        // Pairwise tree, depth 3 on float4 lanes + depth 2 horizontal.
        float4 s0, s1, s;
        s0.x = a.x + b.x;  s0.y = a.y + b.y;  s0.z = a.z + b.z;  s0.w = a.w + b.w;
        s1.x = c.x + d.x;  s1.y = c.y + d.y;  s1.z = c.z + d.z;  s1.w = c.w + d.w;
        float4 s2, s3;
        s2.x = e.x + f.x;  s2.y = e.y + f.y;  s2.z = e.z + f.z;  s2.w = e.w + f.w;
        s3.x = g.x + h.x;  s3.y = g.y + h.y;  s3.z = g.z + h.z;  s3.w = g.w + h.w;
        s0.x += s1.x;  s0.y += s1.y;  s0.z += s1.z;  s0.w += s1.w;
        s2.x += s3.x;  s2.y += s3.y;  s2.z += s3.z;  s2.w += s3.w;
        s.x = s0.x + s2.x;  s.y = s0.y + s2.y;
        s.z = s0.z + s2.z;  s.w = s0.w + s2.w;

        out[t] = (s.x + s.y) + (s.z + s.w);
    }
}

extern "C" void kernel_launch(void* const* d_in, const int* in_sizes, int n_in,
                              void* d_out, int out_size) {
    const float* x        = (const float*)d_in[0];   // [1,4] float32
    const float* matrices = (const float*)d_in[1];   // [100,4,4] float32
    float* out            = (float*)d_out;           // [4] float32

    bigfanout_kernel<<<1, 32>>>(x, matrices, out);
}